// round 14
// baseline (speedup 1.0000x reference)
#include <cuda_runtime.h>

// out[b, i, c] = (1/(i+1)) * sum_{j<=i} x[b, j, c]
// (weights = softmax of causal-masked zeros == running-mean operator; the
//  256 MB weights input is mathematically redundant and never read.)
//
// Single-kernel, single-role decoupled scan (deterministic):
//   each of 1024 blocks owns one 128-row group of one batch:
//     1. batched float4 loads (x read ONCE from DRAM), register scan
//     2. publish group-sum vector + flag (release) immediately
//     3. polite wait on in-batch predecessor flags only (1 flag/thread,
//        __nanosleep backoff, single acquire fence)
//     4. fixed-order lookback prefix (bitwise deterministic every replay)
//     5. scale by 1/(i+1), streaming stores
//   flags self-reset per batch -> graph-replayable with zeroed device state.

namespace {
constexpr int B    = 16;
constexpr int T    = 8192;
constexpr int C    = 64;
constexpr int CG   = C / 4;             // 16 float4 per row (256 B)
constexpr int TILE = 16;                // rows per thread
constexpr int SUBS = 8;                 // thread-columns per block
constexpr int ROWS = TILE * SUBS;       // 128 rows per group
constexpr int NG   = T / ROWS;          // 64 groups per batch
constexpr int GRID = B * NG;            // 1024 blocks, single wave
constexpr int THREADS = CG * SUBS;      // 128 threads
}

__device__ float4 g_bsum[GRID * CG];    // per-(group, c4) sums (256 KB)
__device__ int    g_flag[GRID];         // 1 = group sum published
__device__ int    g_done[B];            // per-batch reset counter

__global__ void __launch_bounds__(THREADS)
k_fused(const float4* __restrict__ x, float4* __restrict__ out) {
    const int blk = blockIdx.x;                    // b*NG + g
    const int g   = blk & (NG - 1);
    const int b   = blk >> 6;
    const int gbase = blk - g;
    const int tid = threadIdx.x;
    const int c4  = tid & (CG - 1);
    const int sub = tid >> 4;                      // 0..7

    const size_t base = (size_t)blk * ROWS * CG + (size_t)sub * TILE * CG + c4;

    // ---- 1. batched loads (x read once), in-register inclusive scan -------
    float4 v[TILE];
#pragma unroll
    for (int t = 0; t < TILE; ++t) v[t] = __ldcg(x + base + (size_t)t * CG);
#pragma unroll
    for (int t = 1; t < TILE; ++t) {
        v[t].x += v[t-1].x; v[t].y += v[t-1].y;
        v[t].z += v[t-1].z; v[t].w += v[t-1].w;
    }

    // ---- 2. publish group sum ASAP ---------------------------------------
    __shared__ float4 s_tsum[SUBS][CG];
    s_tsum[sub][c4] = v[TILE-1];
    __syncthreads();
    if (sub == 0) {                                // fixed combine order
        float4 tot = s_tsum[0][c4];
#pragma unroll
        for (int r = 1; r < SUBS; ++r) {
            tot.x += s_tsum[r][c4].x; tot.y += s_tsum[r][c4].y;
            tot.z += s_tsum[r][c4].z; tot.w += s_tsum[r][c4].w;
        }
        g_bsum[blk * CG + c4] = tot;
        __threadfence();                           // release this lane's sum
        __syncwarp(0x0000FFFFu);
        if (c4 == 0) *(volatile int*)&g_flag[blk] = 1;
    }

    // ---- 3. polite wait: thread p (< g) polls exactly one pred flag -------
    if (tid < g) {
        volatile int* f = &g_flag[gbase + tid];
        if (*f == 0) {
            while (*f == 0) __nanosleep(64);
        }
        __threadfence();                           // acquire
    }
    __syncthreads();

    // ---- 4. deterministic lookback prefix --------------------------------
    // thread (sub, c4): preds p = sub, sub+8, ... < g in fixed order.
    float4 pre = make_float4(0.f, 0.f, 0.f, 0.f);
    for (int p = sub; p < g; p += SUBS) {
        float4 w = __ldcg(&g_bsum[(gbase + p) * CG + c4]);
        pre.x += w.x; pre.y += w.y; pre.z += w.z; pre.w += w.w;
    }

    __shared__ float4 s_pex[SUBS][CG];
    s_pex[sub][c4] = pre;
    __syncthreads();

    float4 acc = s_pex[0][c4];
#pragma unroll
    for (int r = 1; r < SUBS; ++r) {
        acc.x += s_pex[r][c4].x; acc.y += s_pex[r][c4].y;
        acc.z += s_pex[r][c4].z; acc.w += s_pex[r][c4].w;
    }
#pragma unroll
    for (int r = 0; r < SUBS; ++r) {               // lower-sub totals, fixed order
        if (r < sub) {
            acc.x += s_tsum[r][c4].x; acc.y += s_tsum[r][c4].y;
            acc.z += s_tsum[r][c4].z; acc.w += s_tsum[r][c4].w;
        }
    }

    // ---- self-reset: last block of batch clears its flags ----------------
    __syncthreads();                               // all flag/bsum reads done
    if (tid == 0) {
        __threadfence();
        if (atomicAdd(&g_done[b], 1) == NG - 1) {
            for (int p = 0; p < NG; ++p) g_flag[gbase + p] = 0;
            atomicExch(&g_done[b], 0);
        }
    }

    // ---- 5. scale + streaming stores -------------------------------------
    const int row0 = (g * SUBS + sub) * TILE;      // row within batch
#pragma unroll
    for (int t = 0; t < TILE; ++t) {
        const float inv = __fdividef(1.0f, (float)(row0 + t + 1));
        float4 o;
        o.x = (acc.x + v[t].x) * inv;
        o.y = (acc.y + v[t].y) * inv;
        o.z = (acc.z + v[t].z) * inv;
        o.w = (acc.w + v[t].w) * inv;
        __stcs(out + base + (size_t)t * CG, o);
    }
}

// ---------------------------------------------------------------------------
extern "C" void kernel_launch(void* const* d_in, const int* in_sizes, int n_in,
                              void* d_out, int out_size) {
    (void)in_sizes; (void)n_in; (void)out_size;
    const float4* x   = (const float4*)d_in[0];   // [B, T, C] fp32
    float4*       out = (float4*)d_out;           // [B, T, C] fp32
    // d_in[1] (weights, 256 MB) is intentionally unused.

    k_fused<<<GRID, THREADS>>>(x, out);
}

// round 15
// speedup vs baseline: 1.4991x; 1.4991x over previous
#include <cuda_runtime.h>
#include <cstdint>

// out[b, i, c] = (1/(i+1)) * sum_{j<=i} x[b, j, c]
// (weights = softmax of causal-masked zeros == running-mean operator; the
//  256 MB weights input is mathematically redundant and never read.)
//
// Proven 3-kernel scan (R7/R11 structure). This round: k1's global reads go
// through cp.async.bulk (TMA bulk path, 32 KB/block) to test whether the
// ~3.7 TB/s LDG read wall is request-granularity-bound on the DRAM side.

namespace {
constexpr int B    = 16;
constexpr int T    = 8192;
constexpr int C    = 64;
constexpr int CG   = C / 4;            // 16 float4 per row (256 B)
constexpr int TILE = 16;               // rows per tile
constexpr int NT   = T / TILE;         // 512 tiles per batch
constexpr int SUBS = 8;                // tiles handled per block
constexpr int THREADS = CG * SUBS;     // 128 threads
constexpr int GRID = (B * NT) / SUBS;  // 1024 blocks
constexpr int LINES = B * CG;          // 256 independent scan lines
constexpr int TPL   = NT / 32;         // 16 tiles per lane in pass-2 warp scan
constexpr int BLK_BYTES = SUBS * TILE * C * 4;   // 32 KB per block
}

// Scratch: per-(b, tile, channel-group) partial sums, then exclusive prefixes.
__device__ float4 g_part[B * NT * CG];   // 2 MB

__device__ __forceinline__ uint32_t smem_u32(const void* p) {
    uint32_t a;
    asm("{ .reg .u64 t; cvta.to.shared.u64 t, %1; cvt.u32.u64 %0, t; }"
        : "=r"(a) : "l"(p));
    return a;
}

// ---------------------------------------------------------------------------
// Pass 1: bulk-async load 32 KB tile-group into smem, then per-thread 16-row
// reduction. Thread (sub, c4) owns tile blk*SUBS+sub, channel-group c4.
// ---------------------------------------------------------------------------
__global__ void __launch_bounds__(THREADS) k_tilesum(const float4* __restrict__ x) {
    __shared__ alignas(128) unsigned char buf[BLK_BYTES];
    __shared__ alignas(8)  unsigned long long mbar;

    const int tid = threadIdx.x;
    const int c4  = tid & (CG - 1);
    const int sub = tid >> 4;
    const int blk = blockIdx.x;                    // covers tiles [blk*8, blk*8+8)

    const uint32_t mb = smem_u32(&mbar);
    const uint32_t db = smem_u32(buf);

    if (tid == 0) {
        asm volatile("mbarrier.init.shared.b64 [%0], %1;" :: "r"(mb), "r"(1));
    }
    __syncthreads();

    if (tid == 0) {
        asm volatile("mbarrier.arrive.expect_tx.shared.b64 _, [%0], %1;"
                     :: "r"(mb), "r"((uint32_t)BLK_BYTES) : "memory");
        const char* src = (const char*)x + (size_t)blk * BLK_BYTES;
        asm volatile(
            "cp.async.bulk.shared::cta.global.mbarrier::complete_tx::bytes "
            "[%0], [%1], %2, [%3];"
            :: "r"(db), "l"(src), "r"((uint32_t)BLK_BYTES), "r"(mb) : "memory");
    }

    // All threads wait (phase 0; fresh barrier each launch -> graph-safe).
    {
        uint32_t done;
        do {
            asm volatile(
                "{\n\t.reg .pred p;\n\t"
                "mbarrier.try_wait.parity.acquire.cta.shared::cta.b64 p, [%1], 0, 0x989680;\n\t"
                "selp.b32 %0, 1, 0, p;\n\t}"
                : "=r"(done) : "r"(mb) : "memory");
        } while (!done);
    }

    // Reduce 16 rows from smem: row r = sub*16+t, offset r*256 + c4*16.
    const float4* bp = (const float4*)(buf) + (size_t)sub * TILE * CG + c4;
    float4 s = make_float4(0.f, 0.f, 0.f, 0.f);
#pragma unroll
    for (int t = 0; t < TILE; ++t) {
        float4 v = bp[t * CG];
        s.x += v.x; s.y += v.y; s.z += v.z; s.w += v.w;
    }
    g_part[(blk * SUBS + sub) * CG + c4] = s;
}

// ---------------------------------------------------------------------------
// Pass 2: exclusive scan of NT=512 tile sums per (b, c4) line.
// One warp per line (256 warps). (Identical to the proven R7 version.)
// ---------------------------------------------------------------------------
__global__ void __launch_bounds__(128) k_scan() {
    const int warp = blockIdx.x * 4 + (threadIdx.x >> 5);   // 0..255 line id
    const int lane = threadIdx.x & 31;
    const int b  = warp / CG;
    const int c4 = warp % CG;

    const int base = (b * NT + lane * TPL) * CG + c4;

    float4 vals[TPL];
#pragma unroll
    for (int k = 0; k < TPL; ++k) vals[k] = g_part[base + k * CG];

    float4 s = make_float4(0.f, 0.f, 0.f, 0.f);
#pragma unroll
    for (int k = 0; k < TPL; ++k) {
        s.x += vals[k].x; s.y += vals[k].y; s.z += vals[k].z; s.w += vals[k].w;
    }

    float4 inc = s;
#pragma unroll
    for (int d = 1; d < 32; d <<= 1) {
        float tx = __shfl_up_sync(0xFFFFFFFFu, inc.x, d);
        float ty = __shfl_up_sync(0xFFFFFFFFu, inc.y, d);
        float tz = __shfl_up_sync(0xFFFFFFFFu, inc.z, d);
        float tw = __shfl_up_sync(0xFFFFFFFFu, inc.w, d);
        if (lane >= d) { inc.x += tx; inc.y += ty; inc.z += tz; inc.w += tw; }
    }
    float4 run;
    run.x = __shfl_up_sync(0xFFFFFFFFu, inc.x, 1);
    run.y = __shfl_up_sync(0xFFFFFFFFu, inc.y, 1);
    run.z = __shfl_up_sync(0xFFFFFFFFu, inc.z, 1);
    run.w = __shfl_up_sync(0xFFFFFFFFu, inc.w, 1);
    if (lane == 0) run = make_float4(0.f, 0.f, 0.f, 0.f);

#pragma unroll
    for (int k = 0; k < TPL; ++k) {
        float4 v = vals[k];
        g_part[base + k * CG] = run;                 // exclusive prefix
        run.x += v.x; run.y += v.y; run.z += v.z; run.w += v.w;
    }
}

// ---------------------------------------------------------------------------
// Pass 3: local prefix scan per tile seeded with the exclusive tile offset,
// scaled by 1/(i+1). (Identical to the proven R11 version.)
// ---------------------------------------------------------------------------
__global__ void __launch_bounds__(THREADS) k_out(const float4* __restrict__ x,
                                                 float4* __restrict__ out) {
    const int c4  = threadIdx.x & (CG - 1);
    const int sub = threadIdx.x / CG;
    const int blk = blockIdx.x * SUBS + sub;       // == b*NT + tile
    const int tile = blk & (NT - 1);
    const size_t base = (size_t)blk * TILE * CG + c4;

    float4 acc = g_part[blk * CG + c4];
    const int t0 = tile * TILE;

#pragma unroll
    for (int t = 0; t < TILE; ++t) {
        float4 v = __ldcg(x + base + (size_t)t * CG);
        acc.x += v.x; acc.y += v.y; acc.z += v.z; acc.w += v.w;
        const float inv = __fdividef(1.0f, (float)(t0 + t + 1));
        float4 o;
        o.x = acc.x * inv; o.y = acc.y * inv; o.z = acc.z * inv; o.w = acc.w * inv;
        __stcs(out + base + (size_t)t * CG, o);
    }
}

// ---------------------------------------------------------------------------
extern "C" void kernel_launch(void* const* d_in, const int* in_sizes, int n_in,
                              void* d_out, int out_size) {
    (void)in_sizes; (void)n_in; (void)out_size;
    const float4* x   = (const float4*)d_in[0];   // [B, T, C] fp32
    float4*       out = (float4*)d_out;           // [B, T, C] fp32
    // d_in[1] (weights, 256 MB) is intentionally unused.

    k_tilesum<<<GRID, THREADS>>>(x);
    k_scan<<<LINES / 4, 128>>>();
    k_out<<<GRID, THREADS>>>(x, out);
}